// round 16
// baseline (speedup 1.0000x reference)
#include <cuda_runtime.h>

#define E_DIM 256
#define H1 32
#define H2 16
#define ROWS_PER_BLK 8
#define EPAD 260            // padded e row stride in words

__device__ __forceinline__ float ex2f(float x) {
    float y;
    asm("ex2.approx.f32 %0, %1;" : "=f"(y) : "f"(x));
    return y;
}
__device__ __forceinline__ float gelu_exact(float x) {
    return 0.5f * x * (1.0f + erff(x * 0.70710678118654752f));
}

// One fused kernel: block owns 8 rows. Phase 1 computes the 8 sigmas
// (per-block, no cross-block redundancy, w1 read via L1-resident coalesced LDG).
// Phase 2 is the measured-best streaming RBF loop.
__global__ __launch_bounds__(512)
void rbf_fused_kernel(const float* __restrict__ z,     // [M, 2]
                      const float* __restrict__ mu,    // [BN, 2]
                      const float* __restrict__ emb,   // [BN, E]
                      const float* __restrict__ w1,    // [E, H1]
                      const float* __restrict__ b1,    // [H1]
                      const float* __restrict__ w2,    // [H1, H2]
                      const float* __restrict__ b2,    // [H2]
                      const float* __restrict__ w3,    // [H2, 1]
                      const float* __restrict__ b3,    // [1]
                      float* __restrict__ out,         // [BN, M]
                      int M, int BN)
{
    __shared__ float  e_sh[ROWS_PER_BLK * EPAD];          // 8 rows, padded
    __shared__ float  part_sh[512];                       // layer-1 k-half partials
    __shared__ float  h1_sh[ROWS_PER_BLK * (H1 + 1)];     // 8 x 33
    __shared__ float  h2_sh[ROWS_PER_BLK * (H2 + 1)];     // 8 x 17
    __shared__ float4 p_sh[ROWS_PER_BLK];

    const int tid     = threadIdx.x;
    const int rowBase = blockIdx.x * ROWS_PER_BLK;
    const int nRows   = min(ROWS_PER_BLK, BN - rowBase);

    // ---- Phase 1a: stage the 8 embedding rows (coalesced float4) ----
    {
        const float4* s = (const float4*)emb + (size_t)rowBase * (E_DIM / 4);
        const size_t base = (size_t)rowBase * (E_DIM / 4);
        const size_t lim  = (size_t)BN * (E_DIM / 4);
        // 8 rows * 64 float4 = 512 = one per thread
        const int rr = tid >> 6;          // local row
        const int cc = tid & 63;          // float4 col
        float4 v = (base + tid < lim) ? s[tid] : make_float4(0, 0, 0, 0);
        *(float4*)&e_sh[rr * EPAD + cc * 4] = v;
    }
    __syncthreads();

    // ---- Phase 1b: layer 1, k split in halves. tid = half*256 + r*32 + h.
    // Warp = fixed (half, r), lanes = h 0..31 -> w1 row read is one 128B line (L1).
    {
        const int half = tid >> 8;          // 0..1
        const int r    = (tid >> 5) & 7;    // local row
        const int h    = tid & 31;
        const float* erow = e_sh + r * EPAD + half * 128;
        const float* w1p  = w1 + (size_t)(half * 128) * H1 + h;
        float acc = 0.0f;
        #pragma unroll 8
        for (int k = 0; k < 128; ++k)
            acc = fmaf(erow[k], __ldg(&w1p[(size_t)k * H1]), acc);
        part_sh[tid] = acc;
    }
    __syncthreads();

    // combine halves + bias + GELU -> h1_sh
    if (tid < 256) {
        const int r = tid >> 5;
        const int h = tid & 31;
        const float v = part_sh[tid] + part_sh[tid + 256] + __ldg(&b1[h]);
        h1_sh[r * (H1 + 1) + h] = gelu_exact(v);
    }
    __syncthreads();

    // ---- Phase 1c: layer 2 ----
    if (tid < 128) {
        const int r = tid >> 4;
        const int j = tid & 15;
        float acc = __ldg(&b2[j]);
        const float* h1r = h1_sh + r * (H1 + 1);
        #pragma unroll
        for (int i = 0; i < H1; ++i)
            acc = fmaf(h1r[i], __ldg(&w2[i * H2 + j]), acc);
        h2_sh[r * (H2 + 1) + j] = gelu_exact(acc);
    }
    __syncthreads();

    // ---- Phase 1d: layer 3 + sigmoid + per-row exponent constants ----
    if (tid < ROWS_PER_BLK) {
        const int r = tid;
        float s = __ldg(&b3[0]);
        const float* h2r = h2_sh + r * (H2 + 1);
        #pragma unroll
        for (int j = 0; j < H2; ++j)
            s = fmaf(h2r[j], __ldg(&w3[j]), s);
        const float sig   = 1.0f / (1.0f + expf(-s));   // accurate, once/row
        const float sigma = 0.1f + 9.9f * sig;
        const float LOG2E = 1.4426950408889634f;
        const float a  = -0.5f * LOG2E / (sigma * sigma);
        const int row = rowBase + r;
        const int rc  = (row < BN) ? row : (BN - 1);
        const float m0 = mu[rc * 2 + 0];
        const float m1 = mu[rc * 2 + 1];
        p_sh[r] = make_float4(a, -2.0f * a * m0, -2.0f * a * m1,
                              a * fmaf(m0, m0, m1 * m1));
    }
    __syncthreads();

    // ---- Phase 2: streaming RBF (R6 measured-best form) ----
    const int nQuads = M >> 2;
    const float4* __restrict__ z4 = (const float4*)z;

    for (int q = tid; q < nQuads; q += blockDim.x) {
        const float4 za = z4[2 * q];        // (z0,z1) of m=4q, 4q+1
        const float4 zb = z4[2 * q + 1];    // (z0,z1) of m=4q+2, 4q+3

        const float r0 = fmaf(za.x, za.x, za.y * za.y);
        const float r1 = fmaf(za.z, za.z, za.w * za.w);
        const float r2 = fmaf(zb.x, zb.x, zb.y * zb.y);
        const float r3 = fmaf(zb.z, zb.z, zb.w * zb.w);

        float4* out4 = (float4*)out + (size_t)rowBase * nQuads + q;

        #pragma unroll
        for (int r = 0; r < ROWS_PER_BLK; ++r) {
            if (r >= nRows) break;
            const float4 p = p_sh[r];
            float4 o;
            o.x = ex2f(fmaf(p.x, r0, fmaf(p.y, za.x, fmaf(p.z, za.y, p.w))));
            o.y = ex2f(fmaf(p.x, r1, fmaf(p.y, za.z, fmaf(p.z, za.w, p.w))));
            o.z = ex2f(fmaf(p.x, r2, fmaf(p.y, zb.x, fmaf(p.z, zb.y, p.w))));
            o.w = ex2f(fmaf(p.x, r3, fmaf(p.y, zb.z, fmaf(p.z, zb.w, p.w))));
            out4[(size_t)r * nQuads] = o;
        }
    }
}

extern "C" void kernel_launch(void* const* d_in, const int* in_sizes, int n_in,
                              void* d_out, int out_size)
{
    // metadata order: z, mu, embeddings, w1, b1, w2, b2, w3, b3
    const float* z   = (const float*)d_in[0];
    const float* mu  = (const float*)d_in[1];
    const float* emb = (const float*)d_in[2];
    const float* w1  = (const float*)d_in[3];
    const float* b1  = (const float*)d_in[4];
    const float* w2  = (const float*)d_in[5];
    const float* b2  = (const float*)d_in[6];
    const float* w3  = (const float*)d_in[7];
    const float* b3  = (const float*)d_in[8];
    float* out = (float*)d_out;

    const int M  = in_sizes[0] / 2;      // z is [M, 2]
    const int BN = in_sizes[2] / E_DIM;  // embeddings is [BN, E]

    const int blocks = (BN + ROWS_PER_BLK - 1) / ROWS_PER_BLK;
    rbf_fused_kernel<<<blocks, 512>>>(z, mu, emb, w1, b1, w2, b2, w3, b3, out, M, BN);
}

// round 17
// speedup vs baseline: 1.3892x; 1.3892x over previous
#include <cuda_runtime.h>

#define E_DIM 256
#define H1 32
#define H2 16
#define SIG_ROWS 32          // rows per sigma group / producer block
#define EPAD 260             // padded e row stride in words (bank spread)
#define ROWS_PER_BLK 8       // stream rows per block
#define MAX_ROWS 32768
#define MAX_GROUPS (MAX_ROWS / SIG_ROWS)

// Per-row precomputed exponent constants (base-2, log2e folded in):
//   exponent(m) = a*r2[m] + k0*z0[m] + k1*z1[m] + c,  r2 = z0^2+z1^2
__device__ float4 g_params[MAX_ROWS];
__device__ int    g_flag[MAX_GROUPS];   // zero-initialized at module load

__device__ __forceinline__ float ex2f(float x) {
    float y;
    asm("ex2.approx.f32 %0, %1;" : "=f"(y) : "f"(x));
    return y;
}
__device__ __forceinline__ float gelu_exact(float x) {
    return 0.5f * x * (1.0f + erff(x * 0.70710678118654752f));
}

__global__ __launch_bounds__(512, 2)
void rbf_overlap_kernel(const float* __restrict__ z,     // [M, 2]
                        const float* __restrict__ mu,    // [BN, 2]
                        const float* __restrict__ emb,   // [BN, E]
                        const float* __restrict__ w1,    // [E, H1]
                        const float* __restrict__ b1,    // [H1]
                        const float* __restrict__ w2,    // [H1, H2]
                        const float* __restrict__ b2,    // [H2]
                        const float* __restrict__ w3,    // [H2, 1]
                        const float* __restrict__ b3,    // [1]
                        float* __restrict__ out,         // [BN, M]
                        int M, int BN, int nGroups)
{
    __shared__ float  e_sh[SIG_ROWS * EPAD];   // ~33 KB (producer phase only)
    __shared__ float4 p_sh[ROWS_PER_BLK];

    const int bid = blockIdx.x;
    const int tid = threadIdx.x;

    // ================= Producer phase: sigma for group `bid` =================
    if (bid < nGroups) {
        const int rowBase = bid * SIG_ROWS;

        // Stage 32 embedding rows (2048 float4, 512 threads -> 4 iters)
        {
            const float4* s = (const float4*)emb;
            const size_t base = (size_t)rowBase * (E_DIM / 4);
            const size_t lim  = (size_t)BN * (E_DIM / 4);
            #pragma unroll
            for (int i = 0; i < (SIG_ROWS * E_DIM / 4) / 512; ++i) {
                const int idx = tid + i * 512;
                const int rr = idx >> 6;
                const int cc = idx & 63;
                float4 v = (base + idx < lim) ? s[base + idx]
                                              : make_float4(0, 0, 0, 0);
                *(float4*)&e_sh[rr * EPAD + cc * 4] = v;
            }
        }
        __syncthreads();

        if (tid < 256) {
            const int lrow = tid >> 3;    // 0..31
            const int g    = tid & 7;     // 0..7, owns h = 4g..4g+3
            const float* erow = e_sh + lrow * EPAD;

            // ---- Layer 1: w1 rows via coalesced LDG.128 (L1-resident) ----
            float ax = 0.f, ay = 0.f, az = 0.f, aw = 0.f;
            #pragma unroll 8
            for (int k = 0; k < E_DIM; ++k) {
                const float ek = erow[k];                          // broadcast LDS
                const float4 w = __ldg((const float4*)(w1 + k * H1 + g * 4));
                ax = fmaf(ek, w.x, ax);
                ay = fmaf(ek, w.y, ay);
                az = fmaf(ek, w.z, az);
                aw = fmaf(ek, w.w, aw);
            }

            float h1v[4];
            {
                const float4 bb = __ldg((const float4*)&b1[g * 4]);
                h1v[0] = gelu_exact(ax + bb.x);
                h1v[1] = gelu_exact(ay + bb.y);
                h1v[2] = gelu_exact(az + bb.z);
                h1v[3] = gelu_exact(aw + bb.w);
            }

            // ---- Layer 2: partials over my 4 i's for all 16 j ----
            float acc2[16];
            #pragma unroll
            for (int j = 0; j < 16; ++j) acc2[j] = 0.0f;
            #pragma unroll
            for (int ii = 0; ii < 4; ++ii) {
                const int i = g * 4 + ii;
                const float hv = h1v[ii];
                const float4* w2r = (const float4*)(w2 + i * H2);
                #pragma unroll
                for (int jq = 0; jq < 4; ++jq) {
                    const float4 w = __ldg(&w2r[jq]);
                    acc2[jq * 4 + 0] = fmaf(hv, w.x, acc2[jq * 4 + 0]);
                    acc2[jq * 4 + 1] = fmaf(hv, w.y, acc2[jq * 4 + 1]);
                    acc2[jq * 4 + 2] = fmaf(hv, w.z, acc2[jq * 4 + 2]);
                    acc2[jq * 4 + 3] = fmaf(hv, w.w, acc2[jq * 4 + 3]);
                }
            }
            #pragma unroll
            for (int j = 0; j < 16; ++j) {
                acc2[j] += __shfl_xor_sync(0xffffffffu, acc2[j], 1);
                acc2[j] += __shfl_xor_sync(0xffffffffu, acc2[j], 2);
                acc2[j] += __shfl_xor_sync(0xffffffffu, acc2[j], 4);
            }

            // ---- Layer 3: thread g handles j = 2g, 2g+1 ----
            float part;
            {
                const int j0 = g * 2;
                const float h2a = gelu_exact(acc2[j0 + 0] + __ldg(&b2[j0 + 0]));
                const float h2b = gelu_exact(acc2[j0 + 1] + __ldg(&b2[j0 + 1]));
                part = fmaf(h2a, __ldg(&w3[j0]), h2b * __ldg(&w3[j0 + 1]));
            }
            part += __shfl_xor_sync(0xffffffffu, part, 1);
            part += __shfl_xor_sync(0xffffffffu, part, 2);
            part += __shfl_xor_sync(0xffffffffu, part, 4);

            const int row = rowBase + lrow;
            if (g == 0 && row < BN) {
                const float s     = part + __ldg(&b3[0]);
                const float sig   = 1.0f / (1.0f + expf(-s));
                const float sigma = 0.1f + 9.9f * sig;
                const float LOG2E = 1.4426950408889634f;
                const float a  = -0.5f * LOG2E / (sigma * sigma);
                const float m0 = mu[row * 2 + 0];
                const float m1 = mu[row * 2 + 1];
                g_params[row] = make_float4(a, -2.0f * a * m0, -2.0f * a * m1,
                                            a * fmaf(m0, m0, m1 * m1));
            }
        }
        __threadfence();      // all threads: make g_params visible at GPU scope
        __syncthreads();
        if (tid == 0) atomicExch(&g_flag[bid], 1);   // publish
    }

    // ================= Consumer phase: stream rows [bid*8, +8) ===============
    const int rowBase = bid * ROWS_PER_BLK;
    if (rowBase >= BN) return;
    const int nRows  = min(ROWS_PER_BLK, BN - rowBase);
    const int grp    = rowBase >> 5;                 // /SIG_ROWS

    if (tid == 0) {
        volatile int* f = g_flag + grp;
        while (*f == 0) __nanosleep(64);
        __threadfence();
    }
    __syncthreads();

    if (tid < (unsigned)nRows)
        p_sh[tid] = g_params[rowBase + tid];
    __syncthreads();

    const int nQuads = M >> 2;
    const float4* __restrict__ z4 = (const float4*)z;

    for (int q = tid; q < nQuads; q += blockDim.x) {
        const float4 za = z4[2 * q];        // (z0,z1) of m=4q, 4q+1
        const float4 zb = z4[2 * q + 1];    // (z0,z1) of m=4q+2, 4q+3

        const float r0 = fmaf(za.x, za.x, za.y * za.y);
        const float r1 = fmaf(za.z, za.z, za.w * za.w);
        const float r2 = fmaf(zb.x, zb.x, zb.y * zb.y);
        const float r3 = fmaf(zb.z, zb.z, zb.w * zb.w);

        float4* out4 = (float4*)out + (size_t)rowBase * nQuads + q;

        #pragma unroll
        for (int r = 0; r < ROWS_PER_BLK; ++r) {
            if (r >= nRows) break;
            const float4 p = p_sh[r];
            float4 o;
            o.x = ex2f(fmaf(p.x, r0, fmaf(p.y, za.x, fmaf(p.z, za.y, p.w))));
            o.y = ex2f(fmaf(p.x, r1, fmaf(p.y, za.z, fmaf(p.z, za.w, p.w))));
            o.z = ex2f(fmaf(p.x, r2, fmaf(p.y, zb.x, fmaf(p.z, zb.y, p.w))));
            o.w = ex2f(fmaf(p.x, r3, fmaf(p.y, zb.z, fmaf(p.z, zb.w, p.w))));
            out4[(size_t)r * nQuads] = o;
        }
    }
}

extern "C" void kernel_launch(void* const* d_in, const int* in_sizes, int n_in,
                              void* d_out, int out_size)
{
    // metadata order: z, mu, embeddings, w1, b1, w2, b2, w3, b3
    const float* z   = (const float*)d_in[0];
    const float* mu  = (const float*)d_in[1];
    const float* emb = (const float*)d_in[2];
    const float* w1  = (const float*)d_in[3];
    const float* b1  = (const float*)d_in[4];
    const float* w2  = (const float*)d_in[5];
    const float* b2  = (const float*)d_in[6];
    const float* w3  = (const float*)d_in[7];
    const float* b3  = (const float*)d_in[8];
    float* out = (float*)d_out;

    const int M  = in_sizes[0] / 2;      // z is [M, 2]
    const int BN = in_sizes[2] / E_DIM;  // embeddings is [BN, E]

    const int nGroups = (BN + SIG_ROWS - 1) / SIG_ROWS;     // 256
    const int nStream = (BN + ROWS_PER_BLK - 1) / ROWS_PER_BLK; // 1024
    const int blocks  = (nStream > nGroups) ? nStream : nGroups;

    rbf_overlap_kernel<<<blocks, 512>>>(z, mu, emb, w1, b1, w2, b2, w3, b3,
                                        out, M, BN, nGroups);
}